// round 1
// baseline (speedup 1.0000x reference)
#include <cuda_runtime.h>

#define R 2048
#define T 4096
#define NBLK 128
#define NTHREADS 256

// Scratch (static __device__ arrays — no allocation anywhere)
__device__ float g_B[(size_t)T * R];   // 32 MB: precomputed input+feedback bias
__device__ float g_X[(size_t)T * R];   // 32 MB: reservoir states (row 0 = zeros)
__device__ int   g_done[T];            // per-step arrival counters

__device__ __forceinline__ int ld_acq(const int* p) {
    int v;
    asm volatile("ld.global.acquire.gpu.b32 %0, [%1];" : "=r"(v) : "l"(p) : "memory");
    return v;
}

// ---------------------------------------------------------------------------
// Kernel 0: reset counters + zero state row 0 (runs every launch: graph-safe)
// ---------------------------------------------------------------------------
__global__ void init_kernel() {
    int tid = blockIdx.x * blockDim.x + threadIdx.x;
    int stride = gridDim.x * blockDim.x;
    for (int n = tid; n < T; n += stride) g_done[n] = (n == 0) ? NBLK : 0;
    for (int i = tid; i < R; i += stride) g_X[i] = 0.0f;
}

// ---------------------------------------------------------------------------
// Kernel 1: B[n][i] = w_in[i,:]@inputs[n] + w_feedb[i,:]@outputs[n-1], n>=1
// ---------------------------------------------------------------------------
__global__ void precomp_kernel(const float* __restrict__ inputs,
                               const float* __restrict__ outputs,
                               const float* __restrict__ w_in,
                               const float* __restrict__ w_feedb) {
    const int i = blockIdx.x * 256 + threadIdx.x;  // 0..2047 (grid.x = 8)
    float wi[8], wf[4];
#pragma unroll
    for (int k = 0; k < 8; k++) wi[k] = w_in[i * 8 + k];
#pragma unroll
    for (int k = 0; k < 4; k++) wf[k] = w_feedb[i * 4 + k];
    int n0 = blockIdx.y * 128;          // grid.y = 32
    int n1 = n0 + 128;
    if (n0 == 0) n0 = 1;
    for (int n = n0; n < n1; n++) {
        float s = 0.0f;
#pragma unroll
        for (int k = 0; k < 8; k++) s = fmaf(wi[k], inputs[n * 8 + k], s);
#pragma unroll
        for (int k = 0; k < 4; k++) s = fmaf(wf[k], outputs[(n - 1) * 4 + k], s);
        g_B[(size_t)n * R + i] = s;
    }
}

// ---------------------------------------------------------------------------
// Kernel 2: persistent recurrence. 128 blocks x 256 threads.
// Block b owns rows [16b, 16b+16). Warp w owns rows 16b+2w, 16b+2w+1.
// Each lane holds 64 W values per row in registers (32 float4 total).
// ---------------------------------------------------------------------------
__global__ __launch_bounds__(NTHREADS, 1)
void recur_kernel(const float* __restrict__ w, const float* __restrict__ noise) {
    const int tid  = threadIdx.x;
    const int warp = tid >> 5;
    const int lane = tid & 31;
    const int r0   = blockIdx.x * 16 + warp * 2;

    // Load W rows into registers once (persist across all 4096 steps)
    float4 w0[16], w1[16];
    const float4* wr0 = reinterpret_cast<const float4*>(w + (size_t)r0 * R);
    const float4* wr1 = reinterpret_cast<const float4*>(w + (size_t)(r0 + 1) * R);
#pragma unroll
    for (int k = 0; k < 16; ++k) {
        w0[k] = wr0[lane + 32 * k];
        w1[k] = wr1[lane + 32 * k];
    }

    for (int n = 1; n < T; ++n) {
        // Prefetch bias + noise (independent of x) before the spin
        float bn0 = 0.f, bn1 = 0.f, nz0 = 0.f, nz1 = 0.f;
        if (lane == 0) {
            bn0 = g_B[(size_t)n * R + r0];
            bn1 = g_B[(size_t)n * R + r0 + 1];
            nz0 = noise[(size_t)n * R + r0];
            nz1 = noise[(size_t)n * R + r0 + 1];
        }

        if (tid == 0) {
            while (ld_acq(&g_done[n - 1]) < NBLK) {}
        }
        __syncthreads();

        const float4* x4 = reinterpret_cast<const float4*>(g_X + (size_t)(n - 1) * R);
        float a0 = 0.f, a1 = 0.f, b0 = 0.f, b1 = 0.f;
#pragma unroll
        for (int k = 0; k < 16; k += 2) {
            float4 xa = x4[lane + 32 * k];
            float4 xb = x4[lane + 32 * (k + 1)];
            a0 = fmaf(w0[k].x, xa.x, a0);   a0 = fmaf(w0[k].y, xa.y, a0);
            a0 = fmaf(w0[k].z, xa.z, a0);   a0 = fmaf(w0[k].w, xa.w, a0);
            a1 = fmaf(w1[k].x, xa.x, a1);   a1 = fmaf(w1[k].y, xa.y, a1);
            a1 = fmaf(w1[k].z, xa.z, a1);   a1 = fmaf(w1[k].w, xa.w, a1);
            b0 = fmaf(w0[k+1].x, xb.x, b0); b0 = fmaf(w0[k+1].y, xb.y, b0);
            b0 = fmaf(w0[k+1].z, xb.z, b0); b0 = fmaf(w0[k+1].w, xb.w, b0);
            b1 = fmaf(w1[k+1].x, xb.x, b1); b1 = fmaf(w1[k+1].y, xb.y, b1);
            b1 = fmaf(w1[k+1].z, xb.z, b1); b1 = fmaf(w1[k+1].w, xb.w, b1);
        }
        float s0 = a0 + b0;
        float s1 = a1 + b1;
#pragma unroll
        for (int off = 16; off > 0; off >>= 1) {
            s0 += __shfl_xor_sync(0xffffffffu, s0, off);
            s1 += __shfl_xor_sync(0xffffffffu, s1, off);
        }
        if (lane == 0) {
            float2 v;
            v.x = tanhf(s0 + bn0) + nz0;
            v.y = tanhf(s1 + bn1) + nz1;
            *reinterpret_cast<float2*>(g_X + (size_t)n * R + r0) = v;
        }
        __syncthreads();
        if (tid == 0) {
            __threadfence();
            atomicAdd(&g_done[n], 1);
        }
    }
}

// ---------------------------------------------------------------------------
// Kernel 3: readout. out[n] = lin_w[:, :R]@x_n + lin_w[:, R:]@u_n + lin_b
// One block per n, 256 threads.
// ---------------------------------------------------------------------------
__global__ void readout_kernel(const float* __restrict__ inputs,
                               const float* __restrict__ lin_w,
                               const float* __restrict__ lin_b,
                               float* __restrict__ out) {
    const int n   = blockIdx.x;
    const int tid = threadIdx.x;
    if (n == 0) {
        if (tid < 4) out[tid] = lin_b[tid];
        return;
    }
    const int FAN = R + 8;  // 2056
    float acc0 = 0.f, acc1 = 0.f, acc2 = 0.f, acc3 = 0.f;
    const float* xr = g_X + (size_t)n * R;
    for (int i = tid; i < R; i += 256) {
        float xv = xr[i];
        acc0 = fmaf(lin_w[0 * FAN + i], xv, acc0);
        acc1 = fmaf(lin_w[1 * FAN + i], xv, acc1);
        acc2 = fmaf(lin_w[2 * FAN + i], xv, acc2);
        acc3 = fmaf(lin_w[3 * FAN + i], xv, acc3);
    }
#pragma unroll
    for (int off = 16; off > 0; off >>= 1) {
        acc0 += __shfl_xor_sync(0xffffffffu, acc0, off);
        acc1 += __shfl_xor_sync(0xffffffffu, acc1, off);
        acc2 += __shfl_xor_sync(0xffffffffu, acc2, off);
        acc3 += __shfl_xor_sync(0xffffffffu, acc3, off);
    }
    __shared__ float red[8][4];
    int warp = tid >> 5, lane = tid & 31;
    if (lane == 0) {
        red[warp][0] = acc0; red[warp][1] = acc1;
        red[warp][2] = acc2; red[warp][3] = acc3;
    }
    __syncthreads();
    if (tid < 4) {
        float s = 0.f;
#pragma unroll
        for (int wp = 0; wp < 8; wp++) s += red[wp][tid];
        float inp = 0.f;
#pragma unroll
        for (int k = 0; k < 8; k++)
            inp = fmaf(lin_w[tid * FAN + R + k], inputs[n * 8 + k], inp);
        out[n * 4 + tid] = s + inp + lin_b[tid];
    }
}

// ---------------------------------------------------------------------------
// Launch: init -> precompute B -> persistent recurrence -> readout
// All plain launches on the capture stream, no sync, no allocation.
// ---------------------------------------------------------------------------
extern "C" void kernel_launch(void* const* d_in, const int* in_sizes, int n_in,
                              void* d_out, int out_size) {
    const float* inputs  = (const float*)d_in[0];
    const float* outputs = (const float*)d_in[1];
    const float* w       = (const float*)d_in[2];
    const float* w_in    = (const float*)d_in[3];
    const float* w_feedb = (const float*)d_in[4];
    const float* lin_w   = (const float*)d_in[5];
    const float* lin_b   = (const float*)d_in[6];
    const float* noise   = (const float*)d_in[7];
    float* out = (float*)d_out;

    init_kernel<<<8, 256>>>();
    precomp_kernel<<<dim3(8, 32), 256>>>(inputs, outputs, w_in, w_feedb);
    recur_kernel<<<NBLK, NTHREADS>>>(w, noise);
    readout_kernel<<<T, 256>>>(inputs, lin_w, lin_b, out);
}